// round 5
// baseline (speedup 1.0000x reference)
#include <cuda_runtime.h>
#include <cuda_fp16.h>

#define NNODES 20000
#define NEDGES 640000
#define HD 128
#define DD 64
#define LL 4
#define NPART 20          // ceil(NNODES/1024)
#define AS 72             // As stride in halves (144B rows)
#define BS 68             // Bt stride in halves (136B rows)

// ---------------- static device scratch ----------------
__device__ __half g_xl[NNODES * HD];     // fp16, gathered per edge
__device__ __half g_xr[NNODES * HD];     // fp16, read once per node
__device__ float  g_xa[NNODES * DD];     // trunk ping (fp32)
__device__ float  g_xb[NNODES * DD];     // trunk pong (fp32)
__device__ int    g_rowptr[NNODES + 1];
__device__ int    g_deg[NNODES];
__device__ int    g_cursor[NNODES];
__device__ int    g_csr_src[NEDGES];
__device__ int    g_part[32];
__device__ int    g_partoff[32];

// trunk selector: 0 = external (pert), 1 = g_xa, 2 = g_xb
__device__ __forceinline__ const float* fin(const float* ext, int s) {
    return s == 0 ? ext : (s == 1 ? g_xa : g_xb);
}
__device__ __forceinline__ float* fout(int s) { return s == 1 ? g_xa : g_xb; }

// ---------------- CSR build ----------------
__global__ void k_zero() {
    int i = blockIdx.x * blockDim.x + threadIdx.x;
    if (i < NNODES) { g_deg[i] = 0; g_cursor[i] = 0; }
}

__global__ void k_hist(const int* __restrict__ dst) {
    int e = blockIdx.x * blockDim.x + threadIdx.x;
    if (e < NEDGES) atomicAdd(&g_deg[dst[e]], 1);
}

__global__ void k_scan_part() {
    __shared__ int sh[1024];
    int b = blockIdx.x, t = threadIdx.x;
    int i = b * 1024 + t;
    int v = (i < NNODES) ? g_deg[i] : 0;
    sh[t] = v;
    __syncthreads();
    for (int off = 1; off < 1024; off <<= 1) {
        int u = (t >= off) ? sh[t - off] : 0;
        __syncthreads();
        sh[t] += u;
        __syncthreads();
    }
    if (i < NNODES) g_rowptr[i + 1] = sh[t];
    if (t == 1023) g_part[b] = sh[1023];
}

__global__ void k_scan_top() {
    int t = threadIdx.x;  // 32 threads
    int own = (t < NPART) ? g_part[t] : 0;
    int v = own;
    for (int off = 1; off < 32; off <<= 1) {
        int u = __shfl_up_sync(0xffffffffu, v, off);
        if (t >= off) v += u;
    }
    if (t < NPART) g_partoff[t] = v - own;  // exclusive
}

__global__ void k_scan_add() {
    int b = blockIdx.x, t = threadIdx.x;
    int i = b * 1024 + t;
    if (b > 0 && i < NNODES) g_rowptr[i + 1] += g_partoff[b];
    if (b == 0 && t == 0) g_rowptr[0] = 0;
}

__global__ void k_scatter(const int* __restrict__ src, const int* __restrict__ dst) {
    int e = blockIdx.x * blockDim.x + threadIdx.x;
    if (e < NEDGES) {
        int d = dst[e];
        int p = g_rowptr[d] + atomicAdd(&g_cursor[d], 1);
        g_csr_src[p] = src[e];
    }
}

// ---------------- mma helper ----------------
__device__ __forceinline__ void mma16816(float* c, unsigned a0, unsigned a1,
                                         unsigned a2, unsigned a3,
                                         unsigned b0, unsigned b1) {
    asm volatile(
        "mma.sync.aligned.m16n8k16.row.col.f32.f16.f16.f32 "
        "{%0,%1,%2,%3}, {%4,%5,%6,%7}, {%8,%9}, {%0,%1,%2,%3};\n"
        : "+f"(c[0]), "+f"(c[1]), "+f"(c[2]), "+f"(c[3])
        : "r"(a0), "r"(a1), "r"(a2), "r"(a3), "r"(b0), "r"(b1));
}

// ---------------- xl/xr GEMM (tensor core):  x[N,64](fp32) @ W[64,128] (+bias) -> fp16 ----------------
// grid.y 0..3: 64-col slab across logical [Wl | Wr] 256 cols
__global__ __launch_bounds__(128) void k_gemm_lr(
    const float* __restrict__ xext, int insel,
    const float* __restrict__ Wl, const float* __restrict__ Wr,
    const float* __restrict__ bl, const float* __restrict__ br)
{
    __shared__ __half As[64 * AS];
    __shared__ __half Bt[64 * BS];   // Bt[n_local][k]
    const float* x = fin(xext, insel);
    int tid = threadIdx.x, wid = tid >> 5, lane = tid & 31;
    int m0 = blockIdx.x * 64;
    int c0 = blockIdx.y * 64;
    bool isL = (c0 < HD);
    const float* W  = isL ? Wl : Wr;
    const float* bv = isL ? bl : br;
    int wc0 = c0 & (HD - 1);

    // load x tile (fp32 -> fp16): 64 rows x 16 float4
    for (int i = tid; i < 1024; i += 128) {
        int r = i >> 4, c4 = i & 15;
        int row = m0 + r;
        float4 v = make_float4(0.f, 0.f, 0.f, 0.f);
        if (row < NNODES) v = ((const float4*)x)[row * 16 + c4];
        __half2 h0 = __floats2half2_rn(v.x, v.y);
        __half2 h1 = __floats2half2_rn(v.z, v.w);
        unsigned u0 = *(unsigned*)&h0, u1 = *(unsigned*)&h1;
        *(unsigned*)&As[r * AS + c4 * 4]     = u0;
        *(unsigned*)&As[r * AS + c4 * 4 + 2] = u1;
    }
    // load + transpose + convert W slab: Bt[n][k]
    for (int i = tid; i < 1024; i += 128) {
        int k = i >> 4, c4 = i & 15;
        float4 v = *(const float4*)&W[k * HD + wc0 + c4 * 4];
        Bt[(c4 * 4 + 0) * BS + k] = __float2half_rn(v.x);
        Bt[(c4 * 4 + 1) * BS + k] = __float2half_rn(v.y);
        Bt[(c4 * 4 + 2) * BS + k] = __float2half_rn(v.z);
        Bt[(c4 * 4 + 3) * BS + k] = __float2half_rn(v.w);
    }
    __syncthreads();

    float acc[8][4];
#pragma unroll
    for (int nt = 0; nt < 8; nt++)
#pragma unroll
        for (int j = 0; j < 4; j++) acc[nt][j] = 0.f;

    int r0 = wid * 16 + (lane >> 2);
    int kc = (lane & 3) * 2;
    int nb = lane >> 2;
#pragma unroll
    for (int ks = 0; ks < 4; ks++) {
        unsigned a0 = *(const unsigned*)&As[r0 * AS + ks * 16 + kc];
        unsigned a1 = *(const unsigned*)&As[(r0 + 8) * AS + ks * 16 + kc];
        unsigned a2 = *(const unsigned*)&As[r0 * AS + ks * 16 + kc + 8];
        unsigned a3 = *(const unsigned*)&As[(r0 + 8) * AS + ks * 16 + kc + 8];
#pragma unroll
        for (int nt = 0; nt < 8; nt++) {
            unsigned b0 = *(const unsigned*)&Bt[(nt * 8 + nb) * BS + ks * 16 + kc];
            unsigned b1 = *(const unsigned*)&Bt[(nt * 8 + nb) * BS + ks * 16 + kc + 8];
            mma16816(acc[nt], a0, a1, a2, a3, b0, b1);
        }
    }

    __half* out = isL ? g_xl : g_xr;
    int colb = (lane & 3) * 2;
    int rowA = m0 + wid * 16 + (lane >> 2);
#pragma unroll
    for (int nt = 0; nt < 8; nt++) {
        int c = wc0 + nt * 8 + colb;
        float bias0 = bv[c], bias1 = bv[c + 1];
        if (rowA < NNODES) {
            __half2 h = __floats2half2_rn(acc[nt][0] + bias0, acc[nt][1] + bias1);
            *(__half2*)&out[rowA * HD + c] = h;
        }
        if (rowA + 8 < NNODES) {
            __half2 h = __floats2half2_rn(acc[nt][2] + bias0, acc[nt][3] + bias1);
            *(__half2*)&out[(rowA + 8) * HD + c] = h;
        }
    }
}

// ---------------- GATv2 attention: 1 warp/node, 4 edge slots x 8 lanes ----------------
// q = lane&7 owns dims [8q..8q+7] of BOTH heads; slot = lane>>3 owns every 4th edge.
__global__ void k_attn(const float* __restrict__ att, const float* __restrict__ bias,
                       int outsel)
{
    int n = (blockIdx.x * blockDim.x + threadIdx.x) >> 5;
    int lane = threadIdx.x & 31;
    if (n >= NNODES) return;
    int q = lane & 7, slot = lane >> 3;

    const uint4* xl4 = (const uint4*)g_xl;

    // xr[n] strips for both heads -> fp32
    float r0[8], r1[8];
    {
        uint4 u0 = ((const uint4*)g_xr)[n * 16 + q];
        uint4 u1 = ((const uint4*)g_xr)[n * 16 + q + 8];
#pragma unroll
        for (int k = 0; k < 4; k++) {
            float2 p0 = __half22float2(((const __half2*)&u0)[k]);
            float2 p1 = __half22float2(((const __half2*)&u1)[k]);
            r0[2 * k] = p0.x; r0[2 * k + 1] = p0.y;
            r1[2 * k] = p1.x; r1[2 * k + 1] = p1.y;
        }
    }
    // att strips
    float a0[8], a1[8];
    {
        float4 v0 = ((const float4*)att)[q * 2];
        float4 v1 = ((const float4*)att)[q * 2 + 1];
        float4 w0 = ((const float4*)att)[16 + q * 2];
        float4 w1 = ((const float4*)att)[16 + q * 2 + 1];
        a0[0] = v0.x; a0[1] = v0.y; a0[2] = v0.z; a0[3] = v0.w;
        a0[4] = v1.x; a0[5] = v1.y; a0[6] = v1.z; a0[7] = v1.w;
        a1[0] = w0.x; a1[1] = w0.y; a1[2] = w0.z; a1[3] = w0.w;
        a1[4] = w1.x; a1[5] = w1.y; a1[6] = w1.z; a1[7] = w1.w;
    }

    float o0[8], o1[8];
#pragma unroll
    for (int i = 0; i < 8; i++) { o0[i] = 0.f; o1[i] = 0.f; }
    float s0 = 0.f, s1 = 0.f;

    int beg = g_rowptr[n], end = g_rowptr[n + 1];
    int deg = end - beg;
    int niter = (deg + 3) >> 2;          // uniform across the warp

    for (int j = 0; j < niter; j++) {
        int e = beg + j * 4 + slot;
        bool valid = e < end;
        int srcI = g_csr_src[valid ? e : beg];
        uint4 u0 = xl4[srcI * 16 + q];
        uint4 u1 = xl4[srcI * 16 + q + 8];
        float v0[8], v1[8];
#pragma unroll
        for (int k = 0; k < 4; k++) {
            float2 p0 = __half22float2(((const __half2*)&u0)[k]);
            float2 p1 = __half22float2(((const __half2*)&u1)[k]);
            v0[2 * k] = p0.x; v0[2 * k + 1] = p0.y;
            v1[2 * k] = p1.x; v1[2 * k + 1] = p1.y;
        }
        float part0 = 0.f, part1 = 0.f;
#pragma unroll
        for (int i = 0; i < 8; i++) {
            float e0 = v0[i] + r0[i]; e0 = fmaxf(e0, 0.2f * e0);
            float e1 = v1[i] + r1[i]; e1 = fmaxf(e1, 0.2f * e1);
            part0 = fmaf(e0, a0[i], part0);
            part1 = fmaf(e1, a1[i], part1);
        }
        // reduce over the 8 lanes of this slot (xor<=4 stays within 8-lane group)
        part0 += __shfl_xor_sync(0xffffffffu, part0, 1);
        part1 += __shfl_xor_sync(0xffffffffu, part1, 1);
        part0 += __shfl_xor_sync(0xffffffffu, part0, 2);
        part1 += __shfl_xor_sync(0xffffffffu, part1, 2);
        part0 += __shfl_xor_sync(0xffffffffu, part0, 4);
        part1 += __shfl_xor_sync(0xffffffffu, part1, 4);
        float w0 = valid ? __expf(part0) : 0.f;
        float w1 = valid ? __expf(part1) : 0.f;
        s0 += w0; s1 += w1;
#pragma unroll
        for (int i = 0; i < 8; i++) {
            o0[i] = fmaf(w0, v0[i], o0[i]);
            o1[i] = fmaf(w1, v1[i], o1[i]);
        }
    }

    // combine the four slots (xor 8, then 16)
    s0 += __shfl_xor_sync(0xffffffffu, s0, 8);
    s1 += __shfl_xor_sync(0xffffffffu, s1, 8);
    s0 += __shfl_xor_sync(0xffffffffu, s0, 16);
    s1 += __shfl_xor_sync(0xffffffffu, s1, 16);
#pragma unroll
    for (int i = 0; i < 8; i++) {
        o0[i] += __shfl_xor_sync(0xffffffffu, o0[i], 8);
        o1[i] += __shfl_xor_sync(0xffffffffu, o1[i], 8);
        o0[i] += __shfl_xor_sync(0xffffffffu, o0[i], 16);
        o1[i] += __shfl_xor_sync(0xffffffffu, o1[i], 16);
    }

    if (slot == 0) {
        float inv0 = (deg > 0) ? (1.f / s0) : 0.f;
        float inv1 = (deg > 0) ? (1.f / s1) : 0.f;
        float res[8];
        const float* bv = bias + q * 8;
#pragma unroll
        for (int i = 0; i < 8; i++) {
            float t = 0.5f * (o0[i] * inv0 + o1[i] * inv1) + bv[i];
            res[i] = t > 0.f ? t : 0.01f * t;
        }
        float* out = fout(outsel) + n * DD + q * 8;
        *(float4*)(out)     = make_float4(res[0], res[1], res[2], res[3]);
        *(float4*)(out + 4) = make_float4(res[4], res[5], res[6], res[7]);
    }
}

// ---------------- final projection (tensor core): x[N,64](fp32) @ Wo[64,64] + bo, leaky -> fp32 ----------------
__global__ __launch_bounds__(128) void k_gemm_o(
    int insel,
    const float* __restrict__ Wo, const float* __restrict__ bo,
    float* __restrict__ out)
{
    __shared__ __half As[64 * AS];
    __shared__ __half Bt[64 * BS];
    const float* x = fin(nullptr, insel);   // insel is 1 or 2 here
    int tid = threadIdx.x, wid = tid >> 5, lane = tid & 31;
    int m0 = blockIdx.x * 64;

    for (int i = tid; i < 1024; i += 128) {
        int r = i >> 4, c4 = i & 15;
        int row = m0 + r;
        float4 v = make_float4(0.f, 0.f, 0.f, 0.f);
        if (row < NNODES) v = ((const float4*)x)[row * 16 + c4];
        __half2 h0 = __floats2half2_rn(v.x, v.y);
        __half2 h1 = __floats2half2_rn(v.z, v.w);
        *(unsigned*)&As[r * AS + c4 * 4]     = *(unsigned*)&h0;
        *(unsigned*)&As[r * AS + c4 * 4 + 2] = *(unsigned*)&h1;
    }
    for (int i = tid; i < 1024; i += 128) {
        int k = i >> 4, c4 = i & 15;
        float4 v = *(const float4*)&Wo[k * DD + c4 * 4];
        Bt[(c4 * 4 + 0) * BS + k] = __float2half_rn(v.x);
        Bt[(c4 * 4 + 1) * BS + k] = __float2half_rn(v.y);
        Bt[(c4 * 4 + 2) * BS + k] = __float2half_rn(v.z);
        Bt[(c4 * 4 + 3) * BS + k] = __float2half_rn(v.w);
    }
    __syncthreads();

    float acc[8][4];
#pragma unroll
    for (int nt = 0; nt < 8; nt++)
#pragma unroll
        for (int j = 0; j < 4; j++) acc[nt][j] = 0.f;

    int r0 = wid * 16 + (lane >> 2);
    int kc = (lane & 3) * 2;
    int nb = lane >> 2;
#pragma unroll
    for (int ks = 0; ks < 4; ks++) {
        unsigned a0 = *(const unsigned*)&As[r0 * AS + ks * 16 + kc];
        unsigned a1 = *(const unsigned*)&As[(r0 + 8) * AS + ks * 16 + kc];
        unsigned a2 = *(const unsigned*)&As[r0 * AS + ks * 16 + kc + 8];
        unsigned a3 = *(const unsigned*)&As[(r0 + 8) * AS + ks * 16 + kc + 8];
#pragma unroll
        for (int nt = 0; nt < 8; nt++) {
            unsigned b0 = *(const unsigned*)&Bt[(nt * 8 + nb) * BS + ks * 16 + kc];
            unsigned b1 = *(const unsigned*)&Bt[(nt * 8 + nb) * BS + ks * 16 + kc + 8];
            mma16816(acc[nt], a0, a1, a2, a3, b0, b1);
        }
    }

    int colb = (lane & 3) * 2;
    int rowA = m0 + wid * 16 + (lane >> 2);
#pragma unroll
    for (int nt = 0; nt < 8; nt++) {
        int c = nt * 8 + colb;
        float bias0 = bo[c], bias1 = bo[c + 1];
        if (rowA < NNODES) {
            float t0 = acc[nt][0] + bias0; t0 = t0 > 0.f ? t0 : 0.01f * t0;
            float t1 = acc[nt][1] + bias1; t1 = t1 > 0.f ? t1 : 0.01f * t1;
            *(float2*)&out[rowA * DD + c] = make_float2(t0, t1);
        }
        if (rowA + 8 < NNODES) {
            float t0 = acc[nt][2] + bias0; t0 = t0 > 0.f ? t0 : 0.01f * t0;
            float t1 = acc[nt][3] + bias1; t1 = t1 > 0.f ? t1 : 0.01f * t1;
            *(float2*)&out[(rowA + 8) * DD + c] = make_float2(t0, t1);
        }
    }
}

// ---------------- launch ----------------
extern "C" void kernel_launch(void* const* d_in, const int* in_sizes, int n_in,
                              void* d_out, int out_size)
{
    const int*   ei   = (const int*)d_in[0];
    const float* pert = (const float*)d_in[2];
    const float* Wl   = (const float*)d_in[3];
    const float* bl   = (const float*)d_in[4];
    const float* Wr   = (const float*)d_in[5];
    const float* br   = (const float*)d_in[6];
    const float* att  = (const float*)d_in[7];
    const float* bias = (const float*)d_in[8];
    const float* Wo   = (const float*)d_in[9];
    const float* bo   = (const float*)d_in[10];
    float* out = (float*)d_out;

    const int* src = ei;
    const int* dst = ei + NEDGES;

    k_zero<<<(NNODES + 255) / 256, 256>>>();
    k_hist<<<(NEDGES + 255) / 256, 256>>>(dst);
    k_scan_part<<<NPART, 1024>>>();
    k_scan_top<<<1, 32>>>();
    k_scan_add<<<NPART, 1024>>>();
    k_scatter<<<(NEDGES + 255) / 256, 256>>>(src, dst);

    // trunk selectors: layer0 reads pert (sel 0); outputs alternate g_xa(1)/g_xb(2)
    for (int l = 0; l < LL; l++) {
        int insel  = (l == 0) ? 0 : (((l - 1) & 1) ? 2 : 1);
        int outsel = (l & 1) ? 2 : 1;
        dim3 g((NNODES + 63) / 64, 4);
        k_gemm_lr<<<g, 128>>>(pert, insel,
                              Wl + (size_t)l * DD * HD, Wr + (size_t)l * DD * HD,
                              bl + (size_t)l * HD,      br + (size_t)l * HD);
        k_attn<<<(NNODES * 32 + 255) / 256, 256>>>(att + (size_t)l * HD,
                                                   bias + (size_t)l * DD, outsel);
    }
    // layer 3 (l=3, odd) wrote g_xb (sel 2)
    k_gemm_o<<<(NNODES + 63) / 64, 128>>>(2, Wo, bo, out);
}

// round 6
// speedup vs baseline: 1.0970x; 1.0970x over previous
#include <cuda_runtime.h>
#include <cuda_fp16.h>

#define NNODES 20000
#define NEDGES 640000
#define HD 128
#define DD 64
#define LL 4
#define AS 72             // As stride in halves (144B rows)
#define BS 68             // Bt stride in halves (136B rows)
#define SCAN_PER 20       // nodes per thread in single-block scan (1024*20 >= 20000)

// ---------------- static device scratch (zero-initialized) ----------------
__device__ __half g_xl[NNODES * HD];
__device__ __half g_xr[NNODES * HD];
__device__ __half g_xa[NNODES * DD];
__device__ __half g_xb[NNODES * DD];
__device__ int    g_rowptr[NNODES + 1];
__device__ int    g_deg[NNODES];      // invariant: zero at entry to k_hist
__device__ int    g_cursor[NNODES];   // invariant: zero at entry to k_scatter
__device__ int    g_csr_src[NEDGES];

__device__ __forceinline__ const __half* hin(int s)  { return s ? g_xb : g_xa; }
__device__ __forceinline__ __half*       hout(int s) { return s ? g_xb : g_xa; }

// ---------------- input conversion: pert fp32 -> g_xa fp16 ----------------
__global__ void k_cvt(const float* __restrict__ pert) {
    int i = blockIdx.x * blockDim.x + threadIdx.x;   // over N*16 float4s
    if (i < NNODES * 16) {
        float4 v = ((const float4*)pert)[i];
        __half2 h0 = __floats2half2_rn(v.x, v.y);
        __half2 h1 = __floats2half2_rn(v.z, v.w);
        uint2 pk;
        pk.x = *(unsigned*)&h0; pk.y = *(unsigned*)&h1;
        ((uint2*)g_xa)[i] = pk;
    }
}

// ---------------- CSR build: 3 kernels ----------------
__global__ void k_hist(const int* __restrict__ dst) {
    int e = blockIdx.x * blockDim.x + threadIdx.x;
    if (e < NEDGES) atomicAdd(&g_deg[dst[e]], 1);
}

// single block, 1024 threads: prefix-sum deg -> rowptr; re-zero deg & cursor
__global__ void k_scan() {
    __shared__ int warp_tot[32];
    int t = threadIdx.x;
    int base = t * SCAN_PER;
    int loc[SCAN_PER];
    int sum = 0;
#pragma unroll
    for (int i = 0; i < SCAN_PER; i++) {
        int idx = base + i;
        int v = (idx < NNODES) ? g_deg[idx] : 0;
        sum += v;
        loc[i] = sum;                    // inclusive within thread
    }
    int lane = t & 31, wid = t >> 5;
    int x = sum;
#pragma unroll
    for (int off = 1; off < 32; off <<= 1) {
        int u = __shfl_up_sync(0xffffffffu, x, off);
        if (lane >= off) x += u;
    }
    if (lane == 31) warp_tot[wid] = x;
    __syncthreads();
    if (wid == 0) {
        int w = warp_tot[lane];
#pragma unroll
        for (int off = 1; off < 32; off <<= 1) {
            int u = __shfl_up_sync(0xffffffffu, w, off);
            if (lane >= off) w += u;
        }
        warp_tot[lane] = w;
    }
    __syncthreads();
    int excl = (x - sum) + (wid > 0 ? warp_tot[wid - 1] : 0);
#pragma unroll
    for (int i = 0; i < SCAN_PER; i++) {
        int idx = base + i;
        if (idx < NNODES) {
            g_rowptr[idx + 1] = excl + loc[i];
            g_deg[idx] = 0;              // restore invariant for next call
            g_cursor[idx] = 0;           // ready for scatter below
        }
    }
    if (t == 0) g_rowptr[0] = 0;
}

__global__ void k_scatter(const int* __restrict__ src, const int* __restrict__ dst) {
    int e = blockIdx.x * blockDim.x + threadIdx.x;
    if (e < NEDGES) {
        int d = dst[e];
        int p = g_rowptr[d] + atomicAdd(&g_cursor[d], 1);
        g_csr_src[p] = src[e];
    }
}

// ---------------- mma helper ----------------
__device__ __forceinline__ void mma16816(float* c, unsigned a0, unsigned a1,
                                         unsigned a2, unsigned a3,
                                         unsigned b0, unsigned b1) {
    asm volatile(
        "mma.sync.aligned.m16n8k16.row.col.f32.f16.f16.f32 "
        "{%0,%1,%2,%3}, {%4,%5,%6,%7}, {%8,%9}, {%0,%1,%2,%3};\n"
        : "+f"(c[0]), "+f"(c[1]), "+f"(c[2]), "+f"(c[3])
        : "r"(a0), "r"(a1), "r"(a2), "r"(a3), "r"(b0), "r"(b1));
}

// ---------------- xl/xr GEMM (tensor core):  x[N,64] @ W[64,128] (+bias) -> fp16 ----------------
__global__ __launch_bounds__(128) void k_gemm_lr(
    int insel,
    const float* __restrict__ Wl, const float* __restrict__ Wr,
    const float* __restrict__ bl, const float* __restrict__ br)
{
    __shared__ __half As[64 * AS];
    __shared__ __half Bt[64 * BS];   // Bt[n_local][k]
    const __half* x = hin(insel);
    int tid = threadIdx.x, wid = tid >> 5, lane = tid & 31;
    int m0 = blockIdx.x * 64;
    int c0 = blockIdx.y * 64;
    bool isL = (c0 < HD);
    const float* W  = isL ? Wl : Wr;
    const float* bv = isL ? bl : br;
    int wc0 = c0 & (HD - 1);

    for (int i = tid; i < 512; i += 128) {
        int r = i >> 3, c8 = i & 7;
        int row = m0 + r;
        uint4 v = make_uint4(0u, 0u, 0u, 0u);
        if (row < NNODES) v = ((const uint4*)x)[row * 8 + c8];
        *(uint4*)&As[r * AS + c8 * 8] = v;
    }
    for (int i = tid; i < 1024; i += 128) {
        int k = i >> 4, c4 = i & 15;
        float4 v = *(const float4*)&W[k * HD + wc0 + c4 * 4];
        Bt[(c4 * 4 + 0) * BS + k] = __float2half_rn(v.x);
        Bt[(c4 * 4 + 1) * BS + k] = __float2half_rn(v.y);
        Bt[(c4 * 4 + 2) * BS + k] = __float2half_rn(v.z);
        Bt[(c4 * 4 + 3) * BS + k] = __float2half_rn(v.w);
    }
    __syncthreads();

    float acc[8][4];
#pragma unroll
    for (int nt = 0; nt < 8; nt++)
#pragma unroll
        for (int j = 0; j < 4; j++) acc[nt][j] = 0.f;

    int r0 = wid * 16 + (lane >> 2);
    int kc = (lane & 3) * 2;
    int nb = lane >> 2;
#pragma unroll
    for (int ks = 0; ks < 4; ks++) {
        unsigned a0 = *(const unsigned*)&As[r0 * AS + ks * 16 + kc];
        unsigned a1 = *(const unsigned*)&As[(r0 + 8) * AS + ks * 16 + kc];
        unsigned a2 = *(const unsigned*)&As[r0 * AS + ks * 16 + kc + 8];
        unsigned a3 = *(const unsigned*)&As[(r0 + 8) * AS + ks * 16 + kc + 8];
#pragma unroll
        for (int nt = 0; nt < 8; nt++) {
            unsigned b0 = *(const unsigned*)&Bt[(nt * 8 + nb) * BS + ks * 16 + kc];
            unsigned b1 = *(const unsigned*)&Bt[(nt * 8 + nb) * BS + ks * 16 + kc + 8];
            mma16816(acc[nt], a0, a1, a2, a3, b0, b1);
        }
    }

    __half* out = isL ? g_xl : g_xr;
    int colb = (lane & 3) * 2;
    int rowA = m0 + wid * 16 + (lane >> 2);
#pragma unroll
    for (int nt = 0; nt < 8; nt++) {
        int c = wc0 + nt * 8 + colb;
        float bias0 = bv[c], bias1 = bv[c + 1];
        if (rowA < NNODES) {
            __half2 h = __floats2half2_rn(acc[nt][0] + bias0, acc[nt][1] + bias1);
            *(__half2*)&out[rowA * HD + c] = h;
        }
        if (rowA + 8 < NNODES) {
            __half2 h = __floats2half2_rn(acc[nt][2] + bias0, acc[nt][3] + bias1);
            *(__half2*)&out[(rowA + 8) * HD + c] = h;
        }
    }
}

// ---------------- GATv2 attention: 1 warp/node, 2 edge slots of 16 lanes ----------------
__global__ void k_attn(const float* __restrict__ att, const float* __restrict__ bias,
                       int outsel)
{
    int n = (blockIdx.x * blockDim.x + threadIdx.x) >> 5;
    int lane = threadIdx.x & 31;
    if (n >= NNODES) return;
    int q = lane & 15, slot = lane >> 4;

    uint4 rr = ((const uint4*)g_xr)[n * 16 + q];
    float2 rA = __half22float2(*(__half2*)&rr.x);
    float2 rB = __half22float2(*(__half2*)&rr.y);
    float2 rC = __half22float2(*(__half2*)&rr.z);
    float2 rD = __half22float2(*(__half2*)&rr.w);

    float4 af0 = ((const float4*)att)[q * 2];
    float4 af1 = ((const float4*)att)[q * 2 + 1];

    float s = 0.f;
    float o0 = 0.f, o1 = 0.f, o2 = 0.f, o3 = 0.f, o4 = 0.f, o5 = 0.f, o6 = 0.f, o7 = 0.f;

    int beg = g_rowptr[n], end = g_rowptr[n + 1];
    int deg = end - beg;
    int niter = (deg + 3) >> 2;          // uniform across the warp

    for (int j = 0; j < niter; j++) {
        int p = beg + slot + j * 4;
#pragma unroll
        for (int ii = 0; ii < 2; ii++) {
            int e = p + ii * 2;
            bool valid = e < end;
            int srcI = g_csr_src[valid ? e : beg];
            uint4 u = ((const uint4*)g_xl)[srcI * 16 + q];
            float2 f0 = __half22float2(*(__half2*)&u.x);
            float2 f1 = __half22float2(*(__half2*)&u.y);
            float2 f2 = __half22float2(*(__half2*)&u.z);
            float2 f3 = __half22float2(*(__half2*)&u.w);

            float e0 = f0.x + rA.x, e1 = f0.y + rA.y;
            float e2 = f1.x + rB.x, e3 = f1.y + rB.y;
            float e4 = f2.x + rC.x, e5 = f2.y + rC.y;
            float e6 = f3.x + rD.x, e7 = f3.y + rD.y;
            e0 = fmaxf(e0, 0.2f * e0); e1 = fmaxf(e1, 0.2f * e1);
            e2 = fmaxf(e2, 0.2f * e2); e3 = fmaxf(e3, 0.2f * e3);
            e4 = fmaxf(e4, 0.2f * e4); e5 = fmaxf(e5, 0.2f * e5);
            e6 = fmaxf(e6, 0.2f * e6); e7 = fmaxf(e7, 0.2f * e7);
            float part = e0 * af0.x;
            part = fmaf(e1, af0.y, part);
            part = fmaf(e2, af0.z, part);
            part = fmaf(e3, af0.w, part);
            part = fmaf(e4, af1.x, part);
            part = fmaf(e5, af1.y, part);
            part = fmaf(e6, af1.z, part);
            part = fmaf(e7, af1.w, part);
            part += __shfl_xor_sync(0xffffffffu, part, 1);
            part += __shfl_xor_sync(0xffffffffu, part, 2);
            part += __shfl_xor_sync(0xffffffffu, part, 4);
            float w = valid ? __expf(part) : 0.f;
            s += w;
            o0 = fmaf(w, f0.x, o0); o1 = fmaf(w, f0.y, o1);
            o2 = fmaf(w, f1.x, o2); o3 = fmaf(w, f1.y, o3);
            o4 = fmaf(w, f2.x, o4); o5 = fmaf(w, f2.y, o5);
            o6 = fmaf(w, f3.x, o6); o7 = fmaf(w, f3.y, o7);
        }
    }

    s  += __shfl_xor_sync(0xffffffffu, s, 16);
    o0 += __shfl_xor_sync(0xffffffffu, o0, 16);
    o1 += __shfl_xor_sync(0xffffffffu, o1, 16);
    o2 += __shfl_xor_sync(0xffffffffu, o2, 16);
    o3 += __shfl_xor_sync(0xffffffffu, o3, 16);
    o4 += __shfl_xor_sync(0xffffffffu, o4, 16);
    o5 += __shfl_xor_sync(0xffffffffu, o5, 16);
    o6 += __shfl_xor_sync(0xffffffffu, o6, 16);
    o7 += __shfl_xor_sync(0xffffffffu, o7, 16);

    float inv = (deg > 0) ? (1.f / s) : 0.f;
    o0 *= inv; o1 *= inv; o2 *= inv; o3 *= inv;
    o4 *= inv; o5 *= inv; o6 *= inv; o7 *= inv;

    o0 = 0.5f * (o0 + __shfl_xor_sync(0xffffffffu, o0, 8));
    o1 = 0.5f * (o1 + __shfl_xor_sync(0xffffffffu, o1, 8));
    o2 = 0.5f * (o2 + __shfl_xor_sync(0xffffffffu, o2, 8));
    o3 = 0.5f * (o3 + __shfl_xor_sync(0xffffffffu, o3, 8));
    o4 = 0.5f * (o4 + __shfl_xor_sync(0xffffffffu, o4, 8));
    o5 = 0.5f * (o5 + __shfl_xor_sync(0xffffffffu, o5, 8));
    o6 = 0.5f * (o6 + __shfl_xor_sync(0xffffffffu, o6, 8));
    o7 = 0.5f * (o7 + __shfl_xor_sync(0xffffffffu, o7, 8));

    if (lane < 8) {
        float4 b0 = ((const float4*)bias)[q * 2];
        float4 b1 = ((const float4*)bias)[q * 2 + 1];
        float t0 = o0 + b0.x; t0 = t0 > 0.f ? t0 : 0.01f * t0;
        float t1 = o1 + b0.y; t1 = t1 > 0.f ? t1 : 0.01f * t1;
        float t2 = o2 + b0.z; t2 = t2 > 0.f ? t2 : 0.01f * t2;
        float t3 = o3 + b0.w; t3 = t3 > 0.f ? t3 : 0.01f * t3;
        float t4 = o4 + b1.x; t4 = t4 > 0.f ? t4 : 0.01f * t4;
        float t5 = o5 + b1.y; t5 = t5 > 0.f ? t5 : 0.01f * t5;
        float t6 = o6 + b1.z; t6 = t6 > 0.f ? t6 : 0.01f * t6;
        float t7 = o7 + b1.w; t7 = t7 > 0.f ? t7 : 0.01f * t7;
        __half2 h0 = __floats2half2_rn(t0, t1);
        __half2 h1 = __floats2half2_rn(t2, t3);
        __half2 h2 = __floats2half2_rn(t4, t5);
        __half2 h3 = __floats2half2_rn(t6, t7);
        uint4 pk;
        pk.x = *(unsigned*)&h0; pk.y = *(unsigned*)&h1;
        pk.z = *(unsigned*)&h2; pk.w = *(unsigned*)&h3;
        ((uint4*)hout(outsel))[n * 8 + q] = pk;
    }
}

// ---------------- final projection (tensor core) ----------------
__global__ __launch_bounds__(128) void k_gemm_o(
    int insel,
    const float* __restrict__ Wo, const float* __restrict__ bo,
    float* __restrict__ out)
{
    __shared__ __half As[64 * AS];
    __shared__ __half Bt[64 * BS];
    const __half* x = hin(insel);
    int tid = threadIdx.x, wid = tid >> 5, lane = tid & 31;
    int m0 = blockIdx.x * 64;

    for (int i = tid; i < 512; i += 128) {
        int r = i >> 3, c8 = i & 7;
        int row = m0 + r;
        uint4 v = make_uint4(0u, 0u, 0u, 0u);
        if (row < NNODES) v = ((const uint4*)x)[row * 8 + c8];
        *(uint4*)&As[r * AS + c8 * 8] = v;
    }
    for (int i = tid; i < 1024; i += 128) {
        int k = i >> 4, c4 = i & 15;
        float4 v = *(const float4*)&Wo[k * DD + c4 * 4];
        Bt[(c4 * 4 + 0) * BS + k] = __float2half_rn(v.x);
        Bt[(c4 * 4 + 1) * BS + k] = __float2half_rn(v.y);
        Bt[(c4 * 4 + 2) * BS + k] = __float2half_rn(v.z);
        Bt[(c4 * 4 + 3) * BS + k] = __float2half_rn(v.w);
    }
    __syncthreads();

    float acc[8][4];
#pragma unroll
    for (int nt = 0; nt < 8; nt++)
#pragma unroll
        for (int j = 0; j < 4; j++) acc[nt][j] = 0.f;

    int r0 = wid * 16 + (lane >> 2);
    int kc = (lane & 3) * 2;
    int nb = lane >> 2;
#pragma unroll
    for (int ks = 0; ks < 4; ks++) {
        unsigned a0 = *(const unsigned*)&As[r0 * AS + ks * 16 + kc];
        unsigned a1 = *(const unsigned*)&As[(r0 + 8) * AS + ks * 16 + kc];
        unsigned a2 = *(const unsigned*)&As[r0 * AS + ks * 16 + kc + 8];
        unsigned a3 = *(const unsigned*)&As[(r0 + 8) * AS + ks * 16 + kc + 8];
#pragma unroll
        for (int nt = 0; nt < 8; nt++) {
            unsigned b0 = *(const unsigned*)&Bt[(nt * 8 + nb) * BS + ks * 16 + kc];
            unsigned b1 = *(const unsigned*)&Bt[(nt * 8 + nb) * BS + ks * 16 + kc + 8];
            mma16816(acc[nt], a0, a1, a2, a3, b0, b1);
        }
    }

    int colb = (lane & 3) * 2;
    int rowA = m0 + wid * 16 + (lane >> 2);
#pragma unroll
    for (int nt = 0; nt < 8; nt++) {
        int c = nt * 8 + colb;
        float bias0 = bo[c], bias1 = bo[c + 1];
        if (rowA < NNODES) {
            float t0 = acc[nt][0] + bias0; t0 = t0 > 0.f ? t0 : 0.01f * t0;
            float t1 = acc[nt][1] + bias1; t1 = t1 > 0.f ? t1 : 0.01f * t1;
            *(float2*)&out[rowA * DD + c] = make_float2(t0, t1);
        }
        if (rowA + 8 < NNODES) {
            float t0 = acc[nt][2] + bias0; t0 = t0 > 0.f ? t0 : 0.01f * t0;
            float t1 = acc[nt][3] + bias1; t1 = t1 > 0.f ? t1 : 0.01f * t1;
            *(float2*)&out[(rowA + 8) * DD + c] = make_float2(t0, t1);
        }
    }
}

// ---------------- launch ----------------
extern "C" void kernel_launch(void* const* d_in, const int* in_sizes, int n_in,
                              void* d_out, int out_size)
{
    const int*   ei   = (const int*)d_in[0];
    const float* pert = (const float*)d_in[2];
    const float* Wl   = (const float*)d_in[3];
    const float* bl   = (const float*)d_in[4];
    const float* Wr   = (const float*)d_in[5];
    const float* br   = (const float*)d_in[6];
    const float* att  = (const float*)d_in[7];
    const float* bias = (const float*)d_in[8];
    const float* Wo   = (const float*)d_in[9];
    const float* bo   = (const float*)d_in[10];
    float* out = (float*)d_out;

    const int* src = ei;
    const int* dst = ei + NEDGES;

    k_cvt<<<(NNODES * 16 + 255) / 256, 256>>>(pert);
    k_hist<<<(NEDGES + 255) / 256, 256>>>(dst);
    k_scan<<<1, 1024>>>();
    k_scatter<<<(NEDGES + 255) / 256, 256>>>(src, dst);

    for (int l = 0; l < LL; l++) {
        int insel  = (l & 1);        // 0 = g_xa, 1 = g_xb
        int outsel = insel ^ 1;
        dim3 g((NNODES + 63) / 64, 4);
        k_gemm_lr<<<g, 128>>>(insel,
                              Wl + (size_t)l * DD * HD, Wr + (size_t)l * DD * HD,
                              bl + (size_t)l * HD,      br + (size_t)l * HD);
        k_attn<<<(NNODES * 32 + 255) / 256, 256>>>(att + (size_t)l * HD,
                                                   bias + (size_t)l * DD, outsel);
    }
    // after 4 layers the last output landed in g_xa (layer 3: insel=1 -> outsel=0)
    k_gemm_o<<<(NNODES + 63) / 64, 128>>>(0, Wo, bo, out);
}

// round 7
// speedup vs baseline: 1.4173x; 1.2919x over previous
#include <cuda_runtime.h>
#include <cuda_fp16.h>

#define NNODES 20000
#define NEDGES 640000
#define HD 128
#define DD 64
#define LL 4
#define NPART 20          // ceil(NNODES/1024)
#define AS 72             // As stride in halves (144B rows)
#define BS 68             // Bt stride in halves (136B rows)

// ---------------- static device scratch (zero-initialized) ----------------
__device__ __half g_xl[NNODES * HD];
__device__ __half g_xr[NNODES * HD];
__device__ __half g_xa[NNODES * DD];
__device__ __half g_xb[NNODES * DD];
__device__ int    g_rowptr[NNODES + 1];
__device__ int    g_deg[NNODES];      // invariant: zero at entry to k_hist
__device__ int    g_cursor[NNODES];   // invariant: zero at entry to k_scatter
__device__ int    g_csr_src[NEDGES];
__device__ int    g_part[32];
__device__ int    g_partoff[32];

__device__ __forceinline__ const __half* hin(int s)  { return s ? g_xb : g_xa; }
__device__ __forceinline__ __half*       hout(int s) { return s ? g_xb : g_xa; }

// ---------------- input conversion: pert fp32 -> g_xa fp16 ----------------
__global__ void k_cvt(const float* __restrict__ pert) {
    int i = blockIdx.x * blockDim.x + threadIdx.x;   // over N*16 float4s
    if (i < NNODES * 16) {
        float4 v = ((const float4*)pert)[i];
        __half2 h0 = __floats2half2_rn(v.x, v.y);
        __half2 h1 = __floats2half2_rn(v.z, v.w);
        uint2 pk;
        pk.x = *(unsigned*)&h0; pk.y = *(unsigned*)&h1;
        ((uint2*)g_xa)[i] = pk;
    }
}

// ---------------- CSR build ----------------
__global__ void k_hist(const int* __restrict__ dst) {
    int i = blockIdx.x * blockDim.x + threadIdx.x;   // over E/4 int4s
    if (i < NEDGES / 4) {
        int4 d = ((const int4*)dst)[i];
        atomicAdd(&g_deg[d.x], 1);
        atomicAdd(&g_deg[d.y], 1);
        atomicAdd(&g_deg[d.z], 1);
        atomicAdd(&g_deg[d.w], 1);
    }
}

// multi-block scan (R4-proven); also re-zeroes deg & cursor for next call
__global__ void k_scan_part() {
    __shared__ int sh[1024];
    int b = blockIdx.x, t = threadIdx.x;
    int i = b * 1024 + t;
    int v = 0;
    if (i < NNODES) {
        v = g_deg[i];
        g_deg[i] = 0;        // restore invariant for next launch
        g_cursor[i] = 0;     // ready for scatter
    }
    sh[t] = v;
    __syncthreads();
    for (int off = 1; off < 1024; off <<= 1) {
        int u = (t >= off) ? sh[t - off] : 0;
        __syncthreads();
        sh[t] += u;
        __syncthreads();
    }
    if (i < NNODES) g_rowptr[i + 1] = sh[t];
    if (t == 1023) g_part[b] = sh[1023];
}

__global__ void k_scan_top() {
    int t = threadIdx.x;  // 32 threads
    int own = (t < NPART) ? g_part[t] : 0;
    int v = own;
    for (int off = 1; off < 32; off <<= 1) {
        int u = __shfl_up_sync(0xffffffffu, v, off);
        if (t >= off) v += u;
    }
    if (t < NPART) g_partoff[t] = v - own;  // exclusive
}

__global__ void k_scan_add() {
    int b = blockIdx.x, t = threadIdx.x;
    int i = b * 1024 + t;
    if (b > 0 && i < NNODES) g_rowptr[i + 1] += g_partoff[b];
    if (b == 0 && t == 0) g_rowptr[0] = 0;
}

__global__ void k_scatter(const int* __restrict__ src, const int* __restrict__ dst) {
    int e = blockIdx.x * blockDim.x + threadIdx.x;
    if (e < NEDGES) {
        int d = dst[e];
        int p = g_rowptr[d] + atomicAdd(&g_cursor[d], 1);
        g_csr_src[p] = src[e];
    }
}

// ---------------- mma helper ----------------
__device__ __forceinline__ void mma16816(float* c, unsigned a0, unsigned a1,
                                         unsigned a2, unsigned a3,
                                         unsigned b0, unsigned b1) {
    asm volatile(
        "mma.sync.aligned.m16n8k16.row.col.f32.f16.f16.f32 "
        "{%0,%1,%2,%3}, {%4,%5,%6,%7}, {%8,%9}, {%0,%1,%2,%3};\n"
        : "+f"(c[0]), "+f"(c[1]), "+f"(c[2]), "+f"(c[3])
        : "r"(a0), "r"(a1), "r"(a2), "r"(a3), "r"(b0), "r"(b1));
}

// ---------------- xl/xr GEMM (tensor core):  x[N,64] @ W[64,128] (+bias) -> fp16 ----------------
__global__ __launch_bounds__(128) void k_gemm_lr(
    int insel,
    const float* __restrict__ Wl, const float* __restrict__ Wr,
    const float* __restrict__ bl, const float* __restrict__ br)
{
    __shared__ __half As[64 * AS];
    __shared__ __half Bt[64 * BS];   // Bt[n_local][k]
    const __half* x = hin(insel);
    int tid = threadIdx.x, wid = tid >> 5, lane = tid & 31;
    int m0 = blockIdx.x * 64;
    int c0 = blockIdx.y * 64;
    bool isL = (c0 < HD);
    const float* W  = isL ? Wl : Wr;
    const float* bv = isL ? bl : br;
    int wc0 = c0 & (HD - 1);

    for (int i = tid; i < 512; i += 128) {
        int r = i >> 3, c8 = i & 7;
        int row = m0 + r;
        uint4 v = make_uint4(0u, 0u, 0u, 0u);
        if (row < NNODES) v = ((const uint4*)x)[row * 8 + c8];
        *(uint4*)&As[r * AS + c8 * 8] = v;
    }
    for (int i = tid; i < 1024; i += 128) {
        int k = i >> 4, c4 = i & 15;
        float4 v = *(const float4*)&W[k * HD + wc0 + c4 * 4];
        Bt[(c4 * 4 + 0) * BS + k] = __float2half_rn(v.x);
        Bt[(c4 * 4 + 1) * BS + k] = __float2half_rn(v.y);
        Bt[(c4 * 4 + 2) * BS + k] = __float2half_rn(v.z);
        Bt[(c4 * 4 + 3) * BS + k] = __float2half_rn(v.w);
    }
    __syncthreads();

    float acc[8][4];
#pragma unroll
    for (int nt = 0; nt < 8; nt++)
#pragma unroll
        for (int j = 0; j < 4; j++) acc[nt][j] = 0.f;

    int r0 = wid * 16 + (lane >> 2);
    int kc = (lane & 3) * 2;
    int nb = lane >> 2;
#pragma unroll
    for (int ks = 0; ks < 4; ks++) {
        unsigned a0 = *(const unsigned*)&As[r0 * AS + ks * 16 + kc];
        unsigned a1 = *(const unsigned*)&As[(r0 + 8) * AS + ks * 16 + kc];
        unsigned a2 = *(const unsigned*)&As[r0 * AS + ks * 16 + kc + 8];
        unsigned a3 = *(const unsigned*)&As[(r0 + 8) * AS + ks * 16 + kc + 8];
#pragma unroll
        for (int nt = 0; nt < 8; nt++) {
            unsigned b0 = *(const unsigned*)&Bt[(nt * 8 + nb) * BS + ks * 16 + kc];
            unsigned b1 = *(const unsigned*)&Bt[(nt * 8 + nb) * BS + ks * 16 + kc + 8];
            mma16816(acc[nt], a0, a1, a2, a3, b0, b1);
        }
    }

    __half* out = isL ? g_xl : g_xr;
    int colb = (lane & 3) * 2;
    int rowA = m0 + wid * 16 + (lane >> 2);
#pragma unroll
    for (int nt = 0; nt < 8; nt++) {
        int c = wc0 + nt * 8 + colb;
        float bias0 = bv[c], bias1 = bv[c + 1];
        if (rowA < NNODES) {
            __half2 h = __floats2half2_rn(acc[nt][0] + bias0, acc[nt][1] + bias1);
            *(__half2*)&out[rowA * HD + c] = h;
        }
        if (rowA + 8 < NNODES) {
            __half2 h = __floats2half2_rn(acc[nt][2] + bias0, acc[nt][3] + bias1);
            *(__half2*)&out[(rowA + 8) * HD + c] = h;
        }
    }
}

// ---------------- GATv2 attention: 1 warp/node, 2 edge slots of 16 lanes ----------------
// half2 logit path (add/leaky/dot), fp32 exp + accumulation.
__global__ void k_attn(const float* __restrict__ att, const float* __restrict__ bias,
                       int outsel)
{
    int n = (blockIdx.x * blockDim.x + threadIdx.x) >> 5;
    int lane = threadIdx.x & 31;
    if (n >= NNODES) return;
    int q = lane & 15, slot = lane >> 4;

    uint4 rr = ((const uint4*)g_xr)[n * 16 + q];
    __half2 r0 = *(__half2*)&rr.x, r1 = *(__half2*)&rr.y;
    __half2 r2 = *(__half2*)&rr.z, r3 = *(__half2*)&rr.w;

    float4 af0 = ((const float4*)att)[q * 2];
    float4 af1 = ((const float4*)att)[q * 2 + 1];
    __half2 a0 = __floats2half2_rn(af0.x, af0.y), a1 = __floats2half2_rn(af0.z, af0.w);
    __half2 a2 = __floats2half2_rn(af1.x, af1.y), a3 = __floats2half2_rn(af1.z, af1.w);
    const __half2 c02 = __floats2half2_rn(0.2f, 0.2f);

    float s = 0.f;
    float o0 = 0.f, o1 = 0.f, o2 = 0.f, o3 = 0.f, o4 = 0.f, o5 = 0.f, o6 = 0.f, o7 = 0.f;

    int beg = g_rowptr[n], end = g_rowptr[n + 1];
    int deg = end - beg;
    int niter = (deg + 3) >> 2;          // uniform across the warp

    for (int j = 0; j < niter; j++) {
        int p = beg + slot + j * 4;
#pragma unroll
        for (int ii = 0; ii < 2; ii++) {
            int e = p + ii * 2;
            bool valid = e < end;
            int srcI = g_csr_src[valid ? e : beg];
            uint4 u = ((const uint4*)g_xl)[srcI * 16 + q];
            __half2 v0 = *(__half2*)&u.x, v1 = *(__half2*)&u.y;
            __half2 v2 = *(__half2*)&u.z, v3 = *(__half2*)&u.w;

            __half2 e0 = __hadd2(v0, r0), e1 = __hadd2(v1, r1);
            __half2 e2 = __hadd2(v2, r2), e3 = __hadd2(v3, r3);
            __half2 l0 = __hmax2(e0, __hmul2(e0, c02));
            __half2 l1 = __hmax2(e1, __hmul2(e1, c02));
            __half2 l2 = __hmax2(e2, __hmul2(e2, c02));
            __half2 l3 = __hmax2(e3, __hmul2(e3, c02));
            __half2 d  = __hmul2(l0, a0);
            d = __hfma2(l1, a1, d);
            d = __hfma2(l2, a2, d);
            d = __hfma2(l3, a3, d);
            float part = __low2float(d) + __high2float(d);
            part += __shfl_xor_sync(0xffffffffu, part, 1);
            part += __shfl_xor_sync(0xffffffffu, part, 2);
            part += __shfl_xor_sync(0xffffffffu, part, 4);
            float w = valid ? __expf(part) : 0.f;
            s += w;
            float2 f0 = __half22float2(v0), f1 = __half22float2(v1);
            float2 f2 = __half22float2(v2), f3 = __half22float2(v3);
            o0 = fmaf(w, f0.x, o0); o1 = fmaf(w, f0.y, o1);
            o2 = fmaf(w, f1.x, o2); o3 = fmaf(w, f1.y, o3);
            o4 = fmaf(w, f2.x, o4); o5 = fmaf(w, f2.y, o5);
            o6 = fmaf(w, f3.x, o6); o7 = fmaf(w, f3.y, o7);
        }
    }

    s  += __shfl_xor_sync(0xffffffffu, s, 16);
    o0 += __shfl_xor_sync(0xffffffffu, o0, 16);
    o1 += __shfl_xor_sync(0xffffffffu, o1, 16);
    o2 += __shfl_xor_sync(0xffffffffu, o2, 16);
    o3 += __shfl_xor_sync(0xffffffffu, o3, 16);
    o4 += __shfl_xor_sync(0xffffffffu, o4, 16);
    o5 += __shfl_xor_sync(0xffffffffu, o5, 16);
    o6 += __shfl_xor_sync(0xffffffffu, o6, 16);
    o7 += __shfl_xor_sync(0xffffffffu, o7, 16);

    float inv = (deg > 0) ? (1.f / s) : 0.f;
    o0 *= inv; o1 *= inv; o2 *= inv; o3 *= inv;
    o4 *= inv; o5 *= inv; o6 *= inv; o7 *= inv;

    o0 = 0.5f * (o0 + __shfl_xor_sync(0xffffffffu, o0, 8));
    o1 = 0.5f * (o1 + __shfl_xor_sync(0xffffffffu, o1, 8));
    o2 = 0.5f * (o2 + __shfl_xor_sync(0xffffffffu, o2, 8));
    o3 = 0.5f * (o3 + __shfl_xor_sync(0xffffffffu, o3, 8));
    o4 = 0.5f * (o4 + __shfl_xor_sync(0xffffffffu, o4, 8));
    o5 = 0.5f * (o5 + __shfl_xor_sync(0xffffffffu, o5, 8));
    o6 = 0.5f * (o6 + __shfl_xor_sync(0xffffffffu, o6, 8));
    o7 = 0.5f * (o7 + __shfl_xor_sync(0xffffffffu, o7, 8));

    if (lane < 8) {
        float4 b0 = ((const float4*)bias)[q * 2];
        float4 b1 = ((const float4*)bias)[q * 2 + 1];
        float t0 = o0 + b0.x; t0 = t0 > 0.f ? t0 : 0.01f * t0;
        float t1 = o1 + b0.y; t1 = t1 > 0.f ? t1 : 0.01f * t1;
        float t2 = o2 + b0.z; t2 = t2 > 0.f ? t2 : 0.01f * t2;
        float t3 = o3 + b0.w; t3 = t3 > 0.f ? t3 : 0.01f * t3;
        float t4 = o4 + b1.x; t4 = t4 > 0.f ? t4 : 0.01f * t4;
        float t5 = o5 + b1.y; t5 = t5 > 0.f ? t5 : 0.01f * t5;
        float t6 = o6 + b1.z; t6 = t6 > 0.f ? t6 : 0.01f * t6;
        float t7 = o7 + b1.w; t7 = t7 > 0.f ? t7 : 0.01f * t7;
        __half2 h0 = __floats2half2_rn(t0, t1);
        __half2 h1 = __floats2half2_rn(t2, t3);
        __half2 h2 = __floats2half2_rn(t4, t5);
        __half2 h3 = __floats2half2_rn(t6, t7);
        uint4 pk;
        pk.x = *(unsigned*)&h0; pk.y = *(unsigned*)&h1;
        pk.z = *(unsigned*)&h2; pk.w = *(unsigned*)&h3;
        ((uint4*)hout(outsel))[n * 8 + q] = pk;
    }
}

// ---------------- final projection (tensor core) ----------------
__global__ __launch_bounds__(128) void k_gemm_o(
    int insel,
    const float* __restrict__ Wo, const float* __restrict__ bo,
    float* __restrict__ out)
{
    __shared__ __half As[64 * AS];
    __shared__ __half Bt[64 * BS];
    const __half* x = hin(insel);
    int tid = threadIdx.x, wid = tid >> 5, lane = tid & 31;
    int m0 = blockIdx.x * 64;

    for (int i = tid; i < 512; i += 128) {
        int r = i >> 3, c8 = i & 7;
        int row = m0 + r;
        uint4 v = make_uint4(0u, 0u, 0u, 0u);
        if (row < NNODES) v = ((const uint4*)x)[row * 8 + c8];
        *(uint4*)&As[r * AS + c8 * 8] = v;
    }
    for (int i = tid; i < 1024; i += 128) {
        int k = i >> 4, c4 = i & 15;
        float4 v = *(const float4*)&Wo[k * DD + c4 * 4];
        Bt[(c4 * 4 + 0) * BS + k] = __float2half_rn(v.x);
        Bt[(c4 * 4 + 1) * BS + k] = __float2half_rn(v.y);
        Bt[(c4 * 4 + 2) * BS + k] = __float2half_rn(v.z);
        Bt[(c4 * 4 + 3) * BS + k] = __float2half_rn(v.w);
    }
    __syncthreads();

    float acc[8][4];
#pragma unroll
    for (int nt = 0; nt < 8; nt++)
#pragma unroll
        for (int j = 0; j < 4; j++) acc[nt][j] = 0.f;

    int r0 = wid * 16 + (lane >> 2);
    int kc = (lane & 3) * 2;
    int nb = lane >> 2;
#pragma unroll
    for (int ks = 0; ks < 4; ks++) {
        unsigned a0 = *(const unsigned*)&As[r0 * AS + ks * 16 + kc];
        unsigned a1 = *(const unsigned*)&As[(r0 + 8) * AS + ks * 16 + kc];
        unsigned a2 = *(const unsigned*)&As[r0 * AS + ks * 16 + kc + 8];
        unsigned a3 = *(const unsigned*)&As[(r0 + 8) * AS + ks * 16 + kc + 8];
#pragma unroll
        for (int nt = 0; nt < 8; nt++) {
            unsigned b0 = *(const unsigned*)&Bt[(nt * 8 + nb) * BS + ks * 16 + kc];
            unsigned b1 = *(const unsigned*)&Bt[(nt * 8 + nb) * BS + ks * 16 + kc + 8];
            mma16816(acc[nt], a0, a1, a2, a3, b0, b1);
        }
    }

    int colb = (lane & 3) * 2;
    int rowA = m0 + wid * 16 + (lane >> 2);
#pragma unroll
    for (int nt = 0; nt < 8; nt++) {
        int c = nt * 8 + colb;
        float bias0 = bo[c], bias1 = bo[c + 1];
        if (rowA < NNODES) {
            float t0 = acc[nt][0] + bias0; t0 = t0 > 0.f ? t0 : 0.01f * t0;
            float t1 = acc[nt][1] + bias1; t1 = t1 > 0.f ? t1 : 0.01f * t1;
            *(float2*)&out[rowA * DD + c] = make_float2(t0, t1);
        }
        if (rowA + 8 < NNODES) {
            float t0 = acc[nt][2] + bias0; t0 = t0 > 0.f ? t0 : 0.01f * t0;
            float t1 = acc[nt][3] + bias1; t1 = t1 > 0.f ? t1 : 0.01f * t1;
            *(float2*)&out[(rowA + 8) * DD + c] = make_float2(t0, t1);
        }
    }
}

// ---------------- launch ----------------
extern "C" void kernel_launch(void* const* d_in, const int* in_sizes, int n_in,
                              void* d_out, int out_size)
{
    const int*   ei   = (const int*)d_in[0];
    const float* pert = (const float*)d_in[2];
    const float* Wl   = (const float*)d_in[3];
    const float* bl   = (const float*)d_in[4];
    const float* Wr   = (const float*)d_in[5];
    const float* br   = (const float*)d_in[6];
    const float* att  = (const float*)d_in[7];
    const float* bias = (const float*)d_in[8];
    const float* Wo   = (const float*)d_in[9];
    const float* bo   = (const float*)d_in[10];
    float* out = (float*)d_out;

    const int* src = ei;
    const int* dst = ei + NEDGES;

    k_cvt<<<(NNODES * 16 + 255) / 256, 256>>>(pert);
    k_hist<<<(NEDGES / 4 + 255) / 256, 256>>>(dst);
    k_scan_part<<<NPART, 1024>>>();
    k_scan_top<<<1, 32>>>();
    k_scan_add<<<NPART, 1024>>>();
    k_scatter<<<(NEDGES + 255) / 256, 256>>>(src, dst);

    for (int l = 0; l < LL; l++) {
        int insel  = (l & 1);        // 0 = g_xa, 1 = g_xb
        int outsel = insel ^ 1;
        dim3 g((NNODES + 63) / 64, 4);
        k_gemm_lr<<<g, 128>>>(insel,
                              Wl + (size_t)l * DD * HD, Wr + (size_t)l * DD * HD,
                              bl + (size_t)l * HD,      br + (size_t)l * HD);
        k_attn<<<(NNODES * 32 + 255) / 256, 256>>>(att + (size_t)l * HD,
                                                   bias + (size_t)l * DD, outsel);
    }
    // after 4 layers the last output landed in g_xa (layer 3: insel=1 -> outsel=0)
    k_gemm_o<<<(NNODES + 63) / 64, 128>>>(0, Wo, bo, out);
}